// round 13
// baseline (speedup 1.0000x reference)
#include <cuda_runtime.h>
#include <cuda_fp16.h>
#include <mma.h>
#include <stdint.h>
#include <stddef.h>
using namespace nvcuda;

#define SEQ 512
#define BATCH 256
#define INSZ 256
#define HID 128
#define GATES 512
#define OUTSZ 1000
#define M_TOT (SEQ*BATCH)
#define NTILES 1024        // 128-row m-tiles; tile = 2t + half
#define LDA 264
#define LDC 68
#define HSTR 136
#define LDX 520            // padded float stride for xbuf rows
#define XBUFB (16*LDX*4)   // 33280 B per x buffer
#define RCTA 16            // recurrence CTAs (16 real rows each)

__device__ __half g_wih[GATES*INSZ];
__device__ __half g_whh16[GATES*HID];
__device__ float  g_bias[GATES];
__device__ float  g_xproj[(size_t)M_TOT*GATES];
__device__ float  g_hlast[BATCH*HID];
__device__ int    g_flags[NTILES];
__device__ int    g_tilectr;

extern __shared__ char dynsm[];

__device__ __forceinline__ uint32_t s2u(const void* p){
    uint32_t a; asm("{ .reg .u64 t; cvta.to.shared.u64 t, %1; cvt.u32.u64 %0, t; }":"=r"(a):"l"(p)); return a;
}
__device__ __forceinline__ void ldsm4(uint32_t* r, uint32_t a){
    asm volatile("ldmatrix.sync.aligned.m8n8.x4.shared.b16 {%0,%1,%2,%3},[%4];"
        :"=r"(r[0]),"=r"(r[1]),"=r"(r[2]),"=r"(r[3]):"r"(a));
}
__device__ __forceinline__ void ldsm2(uint32_t* r, uint32_t a){
    asm volatile("ldmatrix.sync.aligned.m8n8.x2.shared.b16 {%0,%1},[%2];"
        :"=r"(r[0]),"=r"(r[1]):"r"(a));
}
__device__ __forceinline__ void mma16816h(uint32_t* d, const uint32_t* A, const uint32_t* B){
    asm volatile("mma.sync.aligned.m16n8k16.row.col.f16.f16.f16.f16 "
        "{%0,%1},{%2,%3,%4,%5},{%6,%7},{%0,%1};"
        :"+r"(d[0]),"+r"(d[1])
        :"r"(A[0]),"r"(A[1]),"r"(A[2]),"r"(A[3]),"r"(B[0]),"r"(B[1]));
}
__device__ __forceinline__ float tanha(float x){ float r; asm("tanh.approx.f32 %0,%1;":"=f"(r):"f"(x)); return r; }
__device__ __forceinline__ float sigf(float x){ return fmaf(0.5f, tanha(0.5f*x), 0.5f); }
#define CPA16(d,s) asm volatile("cp.async.cg.shared.global [%0],[%1],16;"::"r"(s2u(d)),"l"(s))

__device__ __forceinline__ void waitflag(const int* p){
    while (*(volatile const int*)p == 0) __nanosleep(128);
    __threadfence();
}

// ---------------- prep (also resets flags/counter every run) ----------------
__global__ void k_prep(const float* __restrict__ w_ih, const float* __restrict__ w_hh,
                       const float* __restrict__ b_ih, const float* __restrict__ b_hh){
    int i = blockIdx.x*blockDim.x + threadIdx.x;
    if (i < GATES*INSZ) g_wih[i] = __float2half_rn(w_ih[i]);
    if (i < GATES*HID)  g_whh16[i] = __float2half_rn(w_hh[i]);
    if (i < GATES)      g_bias[i] = b_ih[i] + b_hh[i];
    if (i < NTILES)     g_flags[i] = 0;
    if (i == 0)         g_tilectr = 0;
}

// ---------------- fused producer(gemm) / consumer(recurrence) ----------------
__device__ __forceinline__ void stageB(__half* Bs, int n0, int tid){
    for (int idx=tid; idx<64*32; idx+=512){
        int row=idx>>5, q=idx&31;
        CPA16(Bs + row*LDA + q*8, g_wih + (size_t)(n0+row)*256 + q*8);
    }
}

__global__ void __launch_bounds__(512,1) k_fused(const float* __restrict__ x){
    int bid = blockIdx.x, tid = threadIdx.x;

    if (bid >= RCTA){
        // =============== GEMM producer: tiles off a global counter ===========
        __half* As  = (__half*)dynsm;
        __half* Bs0 = As + 128*LDA;
        __half* Bs1 = Bs0 + 64*LDA;
        float*  Cs  = (float*)(Bs1 + 64*LDA);
        __half* Bsel[2] = {Bs0, Bs1};
        __shared__ int tile_sm;
        int warp=tid>>5, wm=warp>>2, wn=warp&3;        // 16 warps: 4m x 4n
        for(;;){
            if (tid==0) tile_sm = atomicAdd(&g_tilectr, 1);
            __syncthreads();
            int tile = tile_sm;
            if (tile >= NTILES) return;
            int m0 = tile*128;

            stageB(Bs0, 0, tid);
            asm volatile("cp.async.commit_group;");
            for (int idx=tid; idx<128*64; idx+=512){
                int row=idx>>6, q=idx&63;
                float4 v = ((const float4*)(x+(size_t)(m0+row)*INSZ))[q];
                __half2* dst=(__half2*)(As+row*LDA);
                dst[2*q]=__floats2half2_rn(v.x,v.y); dst[2*q+1]=__floats2half2_rn(v.z,v.w);
            }
            for (int nt=0; nt<8; nt++){
                int n0=nt*64;
                if (nt<7){
                    stageB(Bsel[(nt+1)&1], (nt+1)*64, tid);
                    asm volatile("cp.async.commit_group;");
                    asm volatile("cp.async.wait_group 1;");
                } else {
                    asm volatile("cp.async.wait_group 0;");
                }
                __syncthreads();
                __half* Bs = Bsel[nt&1];

                wmma::fragment<wmma::accumulator,16,16,16,float> c[2];
                for (int i=0;i<2;i++) wmma::fill_fragment(c[i],0.0f);
#pragma unroll
                for (int kt=0;kt<16;kt++){
                    int k=kt*16;
                    wmma::fragment<wmma::matrix_a,16,16,16,__half,wmma::row_major> a[2];
                    wmma::fragment<wmma::matrix_b,16,16,16,__half,wmma::col_major> b;
                    for (int i=0;i<2;i++) wmma::load_matrix_sync(a[i],As+(wm*32+i*16)*LDA+k,LDA);
                    wmma::load_matrix_sync(b,Bs+(wn*16)*LDA+k,LDA);
                    for (int i=0;i<2;i++) wmma::mma_sync(c[i],a[i],b,c[i]);
                }
                for (int i=0;i<2;i++)
                    wmma::store_matrix_sync(&Cs[(wm*32+i*16)*LDC+wn*16],c[i],LDC,wmma::mem_row_major);
                __syncthreads();
                for (int t=tid; t<128*16; t+=512){
                    int r=t>>4, cq=t&15;
                    float4 v=((float4*)Cs)[r*(LDC/4)+cq]; int c0=cq*4;
                    v.x+=g_bias[n0+c0]; v.y+=g_bias[n0+c0+1]; v.z+=g_bias[n0+c0+2]; v.w+=g_bias[n0+c0+3];
                    ((float4*)(g_xproj+(size_t)(m0+r)*GATES+n0))[cq]=v;
                }
                __syncthreads();
            }
            if (tid==0){ __threadfence(); atomicExch(&g_flags[tile], 1); }
        }
    }

    // ======== recurrence: 16 CTAs x 16 REAL rows, d0+d1 both used ===========
    __half* wsh = (__half*)dynsm;                      // init only [512][128]
    __half* hb  = (__half*)(dynsm+131072);             // [2][16][HSTR]
    int w=tid>>5, lane=tid&31, l=lane&15;
    for (int i=tid; i<GATES*HID/8; i+=512) ((uint4*)wsh)[i] = ((const uint4*)g_whh16)[i];
    for (int i=tid; i<2*16*HSTR/2; i+=512) ((__half2*)hb)[i] = __floats2half2_rn(0.f,0.f);
    __syncthreads();

    uint32_t B[4][8][2];
#pragma unroll
    for (int g=0; g<4; g++)
#pragma unroll
        for (int ks=0; ks<8; ks++)
            ldsm2(B[g][ks], s2u(wsh + (g*128 + w*8 + (l&7))*128 + ks*16 + (l>>3)*8));
    __syncthreads();                                   // wsh now free -> xbuf ring

    float* xbs[3] = {(float*)dynsm, (float*)(dynsm+XBUFB), (float*)(dynsm+2*XBUFB)};
    int r = lane>>2, cpair=(lane&3)*2, col=w*8+cpair;
    int half = bid>>3;                                 // batch half for flags
    int brow = bid*16;                                 // batch row base
    float ccA0=0.f,ccA1=0.f,ccB0=0.f,ccB1=0.f;
    float hA0=0.f,hA1=0.f,hB0=0.f,hB1=0.f;

#define STAGEX(buf, tt) do{ int rr=tid>>5, seg=tid&31;                              \
    const float* s_=g_xproj+((size_t)(tt)*BATCH+brow+rr)*GATES+seg*16;              \
    float* d_=(buf)+rr*LDX+seg*16;                                                  \
    CPA16(d_,s_); CPA16(d_+4,s_+4); CPA16(d_+8,s_+8); CPA16(d_+12,s_+12);           \
    asm volatile("cp.async.commit_group;"); }while(0)

    // prologue: flags for t=0,1 then stage both
    if (tid<2) waitflag(&g_flags[2*tid+half]);
    __syncthreads();
    STAGEX(xbs[0], 0);
    STAGEX(xbs[1], 1);

    for (int t=0; t<SEQ; t++){
        if ((t&7)==0 && tid<9){                       // confirm flag window [t+2, t+10]
            int tf=t+2+tid; if (tf>SEQ-1) tf=SEQ-1;
            waitflag(&g_flags[2*tf+half]);
        }
        asm volatile("cp.async.wait_group 1;");       // xbuf[t%3] complete
        __syncthreads();                              // + h(t-1) visible

        uint32_t acc[4][2];
#pragma unroll
        for (int g=0; g<4; g++){ acc[g][0]=0u; acc[g][1]=0u; }
        uint32_t hbase = s2u(hb + (t&1)*16*HSTR + l*HSTR + (lane>>4)*8);
#pragma unroll
        for (int ks=0; ks<8; ks++){
            uint32_t A[4];
            ldsm4(A, hbase + ks*32);
#pragma unroll
            for (int g=0; g<4; g++) mma16816h(acc[g], A, B[g][ks]);
        }
        const float* xp = xbs[t%3];
        float2 mA[4], mB[4], xA[4], xB[4];
#pragma unroll
        for (int g=0; g<4; g++){
            mA[g]=__half22float2(*(const __half2*)&acc[g][0]);
            mB[g]=__half22float2(*(const __half2*)&acc[g][1]);
            xA[g]=*(const float2*)(xp + r*LDX + g*128 + col);
            xB[g]=*(const float2*)(xp + (r+8)*LDX + g*128 + col);
        }
        float iA0=sigf(mA[0].x+xA[0].x), iA1=sigf(mA[0].y+xA[0].y);
        float fA0=sigf(mA[1].x+xA[1].x), fA1=sigf(mA[1].y+xA[1].y);
        float gA0=tanha(mA[2].x+xA[2].x), gA1=tanha(mA[2].y+xA[2].y);
        float oA0=sigf(mA[3].x+xA[3].x), oA1=sigf(mA[3].y+xA[3].y);
        ccA0=fA0*ccA0+iA0*gA0; ccA1=fA1*ccA1+iA1*gA1;
        hA0=oA0*tanha(ccA0);   hA1=oA1*tanha(ccA1);
        float iB0=sigf(mB[0].x+xB[0].x), iB1=sigf(mB[0].y+xB[0].y);
        float fB0=sigf(mB[1].x+xB[1].x), fB1=sigf(mB[1].y+xB[1].y);
        float gB0=tanha(mB[2].x+xB[2].x), gB1=tanha(mB[2].y+xB[2].y);
        float oB0=sigf(mB[3].x+xB[3].x), oB1=sigf(mB[3].y+xB[3].y);
        ccB0=fB0*ccB0+iB0*gB0; ccB1=fB1*ccB1+iB1*gB1;
        hB0=oB0*tanha(ccB0);   hB1=oB1*tanha(ccB1);

        __half2* hw = (__half2*)hb + ((t&1)^1)*(16*HSTR/2);
        hw[r*(HSTR/2) + (col>>1)]     = __floats2half2_rn(hA0,hA1);
        hw[(r+8)*(HSTR/2) + (col>>1)] = __floats2half2_rn(hB0,hB1);

        int tq = (t+2<SEQ)? t+2 : SEQ-1;              // always issue (keeps group count)
        STAGEX(xbs[(t+2)%3], tq);
    }
    *(float2*)(g_hlast + (brow+r)*HID + col)   = make_float2(hA0,hA1);
    *(float2*)(g_hlast + (brow+r+8)*HID + col) = make_float2(hB0,hB1);
#undef STAGEX
}

// ---------------- dense + softmax (2 batch rows / block) ----------------
__global__ void __launch_bounds__(512) k_dense2(const float* __restrict__ wd,
                                                const float* __restrict__ bd,
                                                float* __restrict__ out){
    int b0=blockIdx.x*2, tid=threadIdx.x, lane=tid&31, warp=tid>>5;
    __shared__ float hs[2*HID];
    __shared__ float lg[2*OUTSZ];
    __shared__ float red[32];
    if (tid<2*HID) hs[tid]=g_hlast[b0*HID+tid];
    __syncthreads();
    const float4* h0=(const float4*)hs;
    const float4* h1=(const float4*)(hs+HID);
    for (int o=tid; o<OUTSZ; o+=512){
        const float4* wp=(const float4*)(wd+(size_t)o*HID);
        float s0=0.f, s1=0.f;
#pragma unroll 8
        for (int q=0;q<32;q++){
            float4 v=wp[q]; float4 a=h0[q]; float4 b=h1[q];
            s0 += v.x*a.x+v.y*a.y+v.z*a.z+v.w*a.w;
            s1 += v.x*b.x+v.y*b.y+v.z*b.z+v.w*b.w;
        }
        float bb=bd[o];
        lg[o]=s0+bb; lg[OUTSZ+o]=s1+bb;
    }
    __syncthreads();
    float m0=-1e30f, m1=-1e30f;
    for (int i=tid;i<OUTSZ;i+=512){ m0=fmaxf(m0,lg[i]); m1=fmaxf(m1,lg[OUTSZ+i]); }
#pragma unroll
    for (int s=16;s;s>>=1){ m0=fmaxf(m0,__shfl_xor_sync(0xffffffffu,m0,s));
                            m1=fmaxf(m1,__shfl_xor_sync(0xffffffffu,m1,s)); }
    if (lane==0){ red[warp]=m0; red[16+warp]=m1; }
    __syncthreads();
    m0=red[0]; m1=red[16];
#pragma unroll
    for (int ww=1;ww<16;ww++){ m0=fmaxf(m0,red[ww]); m1=fmaxf(m1,red[16+ww]); }
    float s0=0.f, s1=0.f;
    for (int i=tid;i<OUTSZ;i+=512){
        float e0=__expf(lg[i]-m0);       lg[i]=e0;       s0+=e0;
        float e1=__expf(lg[OUTSZ+i]-m1); lg[OUTSZ+i]=e1; s1+=e1;
    }
#pragma unroll
    for (int s=16;s;s>>=1){ s0+=__shfl_xor_sync(0xffffffffu,s0,s);
                            s1+=__shfl_xor_sync(0xffffffffu,s1,s); }
    __syncthreads();
    if (lane==0){ red[warp]=s0; red[16+warp]=s1; }
    __syncthreads();
    s0=red[0]; s1=red[16];
#pragma unroll
    for (int ww=1;ww<16;ww++){ s0+=red[ww]; s1+=red[16+ww]; }
    float inv0=1.0f/s0, inv1=1.0f/s1;
    for (int i=tid;i<OUTSZ;i+=512){
        out[(size_t)b0*OUTSZ+i]     = lg[i]*inv0;
        out[(size_t)(b0+1)*OUTSZ+i] = lg[OUTSZ+i]*inv1;
    }
}

// ---------------- launcher ----------------
extern "C" void kernel_launch(void* const* d_in, const int* in_sizes, int n_in,
                              void* d_out, int out_size){
    const float* x=(const float*)d_in[0];
    const float* wih=(const float*)d_in[1];
    const float* whh=(const float*)d_in[2];
    const float* bih=(const float*)d_in[3];
    const float* bhh=(const float*)d_in[4];
    const float* wd=(const float*)d_in[5];
    const float* bd=(const float*)d_in[6];
    float* out=(float*)d_out;

    int fsm = (128*LDA + 2*64*LDA)*2 + 128*LDC*4;      // 169984 B (gemm max)
    cudaFuncSetAttribute(k_fused, cudaFuncAttributeMaxDynamicSharedMemorySize, fsm);

    k_prep<<<512,256>>>(wih,whh,bih,bhh);
    k_fused<<<148,512,fsm>>>(x);
    k_dense2<<<BATCH/2,512>>>(wd,bd,out);
}

// round 14
// speedup vs baseline: 1.5016x; 1.5016x over previous
#include <cuda_runtime.h>
#include <cuda_fp16.h>
#include <mma.h>
#include <stdint.h>
#include <stddef.h>
using namespace nvcuda;

#define SEQ 512
#define BATCH 256
#define INSZ 256
#define HID 128
#define GATES 512
#define OUTSZ 1000
#define M_TOT (SEQ*BATCH)
#define NTILES 1024        // 128-row m-tiles; tile = 2t + half
#define LDA 264
#define LDC 68
#define HSTR 136

__device__ __half g_wih[GATES*INSZ];
__device__ __half g_whh16[GATES*HID];
__device__ float  g_bias[GATES];
__device__ float  g_xproj[(size_t)M_TOT*GATES];
__device__ float  g_hlast[BATCH*HID];
__device__ int    g_flags[NTILES];
__device__ int    g_tilectr;

extern __shared__ char dynsm[];

__device__ __forceinline__ uint32_t s2u(const void* p){
    uint32_t a; asm("{ .reg .u64 t; cvta.to.shared.u64 t, %1; cvt.u32.u64 %0, t; }":"=r"(a):"l"(p)); return a;
}
__device__ __forceinline__ void ldsm4(uint32_t* r, uint32_t a){
    asm volatile("ldmatrix.sync.aligned.m8n8.x4.shared.b16 {%0,%1,%2,%3},[%4];"
        :"=r"(r[0]),"=r"(r[1]),"=r"(r[2]),"=r"(r[3]):"r"(a));
}
__device__ __forceinline__ void ldsm2(uint32_t* r, uint32_t a){
    asm volatile("ldmatrix.sync.aligned.m8n8.x2.shared.b16 {%0,%1},[%2];"
        :"=r"(r[0]),"=r"(r[1]):"r"(a));
}
__device__ __forceinline__ void mma16816h(uint32_t* d, const uint32_t* A, const uint32_t* B){
    asm volatile("mma.sync.aligned.m16n8k16.row.col.f16.f16.f16.f16 "
        "{%0,%1},{%2,%3,%4,%5},{%6,%7},{%0,%1};"
        :"+r"(d[0]),"+r"(d[1])
        :"r"(A[0]),"r"(A[1]),"r"(A[2]),"r"(A[3]),"r"(B[0]),"r"(B[1]));
}
__device__ __forceinline__ float tanha(float x){ float r; asm("tanh.approx.f32 %0,%1;":"=f"(r):"f"(x)); return r; }
__device__ __forceinline__ float sigf(float x){ return fmaf(0.5f, tanha(0.5f*x), 0.5f); }
#define CPA16(d,s) asm volatile("cp.async.cg.shared.global [%0],[%1],16;"::"r"(s2u(d)),"l"(s))

__device__ __forceinline__ void waitflag(const int* p){
    while (*(volatile const int*)p == 0) __nanosleep(128);
    __threadfence();
}

// ---------------- prep (also resets flags/counter every run) ----------------
__global__ void k_prep(const float* __restrict__ w_ih, const float* __restrict__ w_hh,
                       const float* __restrict__ b_ih, const float* __restrict__ b_hh){
    int i = blockIdx.x*blockDim.x + threadIdx.x;
    if (i < GATES*INSZ) g_wih[i] = __float2half_rn(w_ih[i]);
    if (i < GATES*HID)  g_whh16[i] = __float2half_rn(w_hh[i]);
    if (i < GATES)      g_bias[i] = b_ih[i] + b_hh[i];
    if (i < NTILES)     g_flags[i] = 0;
    if (i == 0)         g_tilectr = 0;
}

// ---------------- fused producer(gemm) / consumer(recurrence) ----------------
__device__ __forceinline__ void stageB(__half* Bs, int n0, int tid){
    for (int idx=tid; idx<64*32; idx+=512){
        int row=idx>>5, q=idx&31;
        CPA16(Bs + row*LDA + q*8, g_wih + (size_t)(n0+row)*256 + q*8);
    }
}

__global__ void __launch_bounds__(512,1) k_fused(const float* __restrict__ x){
    int bid = blockIdx.x, tid = threadIdx.x;

    if (bid >= 32){
        // =============== GEMM producer: tiles off a global counter ===========
        __half* As  = (__half*)dynsm;
        __half* Bs0 = As + 128*LDA;
        __half* Bs1 = Bs0 + 64*LDA;
        float*  Cs  = (float*)(Bs1 + 64*LDA);
        __half* Bsel[2] = {Bs0, Bs1};
        __shared__ int tile_sm;
        int warp=tid>>5, wm=warp>>2, wn=warp&3;        // 16 warps: 4m x 4n
        for(;;){
            if (tid==0) tile_sm = atomicAdd(&g_tilectr, 1);
            __syncthreads();
            int tile = tile_sm;
            if (tile >= NTILES) return;
            int m0 = tile*128;

            stageB(Bs0, 0, tid);
            asm volatile("cp.async.commit_group;");
            for (int idx=tid; idx<128*64; idx+=512){
                int row=idx>>6, q=idx&63;
                float4 v = ((const float4*)(x+(size_t)(m0+row)*INSZ))[q];
                __half2* dst=(__half2*)(As+row*LDA);
                dst[2*q]=__floats2half2_rn(v.x,v.y); dst[2*q+1]=__floats2half2_rn(v.z,v.w);
            }
            for (int nt=0; nt<8; nt++){
                int n0=nt*64;
                if (nt<7){
                    stageB(Bsel[(nt+1)&1], (nt+1)*64, tid);
                    asm volatile("cp.async.commit_group;");
                    asm volatile("cp.async.wait_group 1;");
                } else {
                    asm volatile("cp.async.wait_group 0;");
                }
                __syncthreads();
                __half* Bs = Bsel[nt&1];

                wmma::fragment<wmma::accumulator,16,16,16,float> c[2];
                for (int i=0;i<2;i++) wmma::fill_fragment(c[i],0.0f);
#pragma unroll
                for (int kt=0;kt<16;kt++){
                    int k=kt*16;
                    wmma::fragment<wmma::matrix_a,16,16,16,__half,wmma::row_major> a[2];
                    wmma::fragment<wmma::matrix_b,16,16,16,__half,wmma::col_major> b;
                    for (int i=0;i<2;i++) wmma::load_matrix_sync(a[i],As+(wm*32+i*16)*LDA+k,LDA);
                    wmma::load_matrix_sync(b,Bs+(wn*16)*LDA+k,LDA);
                    for (int i=0;i<2;i++) wmma::mma_sync(c[i],a[i],b,c[i]);
                }
                for (int i=0;i<2;i++)
                    wmma::store_matrix_sync(&Cs[(wm*32+i*16)*LDC+wn*16],c[i],LDC,wmma::mem_row_major);
                __syncthreads();
                for (int t=tid; t<128*16; t+=512){
                    int r=t>>4, cq=t&15;
                    float4 v=((float4*)Cs)[r*(LDC/4)+cq]; int c0=cq*4;
                    v.x+=g_bias[n0+c0]; v.y+=g_bias[n0+c0+1]; v.z+=g_bias[n0+c0+2]; v.w+=g_bias[n0+c0+3];
                    ((float4*)(g_xproj+(size_t)(m0+r)*GATES+n0))[cq]=v;
                }
                __syncthreads();
            }
            if (tid==0){ __threadfence(); atomicExch(&g_flags[tile], 1); }
        }
    }

    // =============== recurrence consumer: 32 CTAs x 8 batch rows =============
    __half* wsh = (__half*)dynsm;                      // init only [512][128]
    __half* hb  = (__half*)(dynsm+131072);             // [2][16][HSTR]
    int w=tid>>5, lane=tid&31, l=lane&15;
    for (int i=tid; i<GATES*HID/8; i+=512) ((uint4*)wsh)[i] = ((const uint4*)g_whh16)[i];
    for (int i=tid; i<2*16*HSTR/2; i+=512) ((__half2*)hb)[i] = __floats2half2_rn(0.f,0.f);
    __syncthreads();

    uint32_t B[4][8][2];
#pragma unroll
    for (int g=0; g<4; g++)
#pragma unroll
        for (int ks=0; ks<8; ks++)
            ldsm2(B[g][ks], s2u(wsh + (g*128 + w*8 + (l&7))*128 + ks*16 + (l>>3)*8));
    __syncthreads();

    int r = lane>>2, cpair=(lane&3)*2, col=w*8+cpair;
    int half = (bid>=16) ? 1 : 0;
    const float* xbase = g_xproj + (size_t)(bid*8 + r)*GATES + col;
    float cc0=0.f, cc1=0.f, h0f=0.f, h1f=0.f;

    // prologue: confirm flags for t=0,1; load cx(t=0), nx(t=1)
    if (tid<2) waitflag(&g_flags[2*tid+half]);
    __syncthreads();
    float2 cx[4], nx[4];
#pragma unroll
    for (int g=0; g<4; g++){
        cx[g] = *(const float2*)(xbase + g*128);
        nx[g] = *(const float2*)(xbase + (size_t)BATCH*GATES + g*128);
    }

    for (int t=0; t<SEQ; t++){
        // windowed flag confirmation: every 8 steps, cover t+2 .. t+10
        if ((t&7)==0 && tid<9){
            int tf=t+2+tid; if (tf>SEQ-1) tf=SEQ-1;
            waitflag(&g_flags[2*tf+half]);
        }
        __syncthreads();                               // h(t-1) visible + flags published

        // prefetch x_proj[t+2] (flag confirmed by current window)
        int tn = (t+2<SEQ)? t+2 : SEQ-1;
        float2 nx2[4];
        {
            const float* nb = xbase + (size_t)tn*BATCH*GATES;
#pragma unroll
            for (int g=0; g<4; g++) nx2[g] = *(const float2*)(nb + g*128);
        }

        uint32_t acc[4][2][2];
#pragma unroll
        for (int g=0; g<4; g++){ acc[g][0][0]=0u; acc[g][0][1]=0u; acc[g][1][0]=0u; acc[g][1][1]=0u; }
        uint32_t hbase = s2u(hb + (t&1)*16*HSTR + l*HSTR + (lane>>4)*8);
        {   // k-halves into independent accumulators: 4-deep chains
            uint32_t A0[4][4];
#pragma unroll
            for (int ks=0; ks<4; ks++) ldsm4(A0[ks], hbase + ks*32);
#pragma unroll
            for (int ks=0; ks<4; ks++)
#pragma unroll
                for (int g=0; g<4; g++) mma16816h(acc[g][0], A0[ks], B[g][ks]);
            uint32_t A1[4][4];
#pragma unroll
            for (int ks=0; ks<4; ks++) ldsm4(A1[ks], hbase + (ks+4)*32);
#pragma unroll
            for (int ks=0; ks<4; ks++)
#pragma unroll
                for (int g=0; g<4; g++) mma16816h(acc[g][1], A1[ks], B[g][ks+4]);
        }
        float2 hv[4];
#pragma unroll
        for (int g=0; g<4; g++){
            float2 u = __half22float2(*(const __half2*)&acc[g][0][0]);
            float2 v = __half22float2(*(const __half2*)&acc[g][1][0]);
            hv[g] = make_float2(u.x+v.x, u.y+v.y);
        }
        float i0=sigf(hv[0].x+cx[0].x), i1=sigf(hv[0].y+cx[0].y);
        float f0=sigf(hv[1].x+cx[1].x), f1=sigf(hv[1].y+cx[1].y);
        float g0=tanha(hv[2].x+cx[2].x), g1=tanha(hv[2].y+cx[2].y);
        float o0=sigf(hv[3].x+cx[3].x), o1=sigf(hv[3].y+cx[3].y);
        cc0 = f0*cc0 + i0*g0;  cc1 = f1*cc1 + i1*g1;
        h0f = o0*tanha(cc0);   h1f = o1*tanha(cc1);
        ((__half2*)hb)[((t&1)^1)*(16*HSTR/2) + r*(HSTR/2) + (col>>1)] = __floats2half2_rn(h0f,h1f);

#pragma unroll
        for (int g=0; g<4; g++){ cx[g]=nx[g]; nx[g]=nx2[g]; }
    }
    *(float2*)(g_hlast + (bid*8 + r)*HID + col) = make_float2(h0f,h1f);
}

// ---------------- dense + softmax (2 batch rows / block) ----------------
__global__ void __launch_bounds__(512) k_dense2(const float* __restrict__ wd,
                                                const float* __restrict__ bd,
                                                float* __restrict__ out){
    int b0=blockIdx.x*2, tid=threadIdx.x, lane=tid&31, warp=tid>>5;
    __shared__ float hs[2*HID];
    __shared__ float lg[2*OUTSZ];
    __shared__ float red[32];
    if (tid<2*HID) hs[tid]=g_hlast[b0*HID+tid];
    __syncthreads();
    const float4* h0=(const float4*)hs;
    const float4* h1=(const float4*)(hs+HID);
    for (int o=tid; o<OUTSZ; o+=512){
        const float4* wp=(const float4*)(wd+(size_t)o*HID);
        float s0=0.f, s1=0.f;
#pragma unroll 8
        for (int q=0;q<32;q++){
            float4 v=wp[q]; float4 a=h0[q]; float4 b=h1[q];
            s0 += v.x*a.x+v.y*a.y+v.z*a.z+v.w*a.w;
            s1 += v.x*b.x+v.y*b.y+v.z*b.z+v.w*b.w;
        }
        float bb=bd[o];
        lg[o]=s0+bb; lg[OUTSZ+o]=s1+bb;
    }
    __syncthreads();
    float m0=-1e30f, m1=-1e30f;
    for (int i=tid;i<OUTSZ;i+=512){ m0=fmaxf(m0,lg[i]); m1=fmaxf(m1,lg[OUTSZ+i]); }
#pragma unroll
    for (int s=16;s;s>>=1){ m0=fmaxf(m0,__shfl_xor_sync(0xffffffffu,m0,s));
                            m1=fmaxf(m1,__shfl_xor_sync(0xffffffffu,m1,s)); }
    if (lane==0){ red[warp]=m0; red[16+warp]=m1; }
    __syncthreads();
    m0=red[0]; m1=red[16];
#pragma unroll
    for (int ww=1;ww<16;ww++){ m0=fmaxf(m0,red[ww]); m1=fmaxf(m1,red[16+ww]); }
    float s0=0.f, s1=0.f;
    for (int i=tid;i<OUTSZ;i+=512){
        float e0=__expf(lg[i]-m0);       lg[i]=e0;       s0+=e0;
        float e1=__expf(lg[OUTSZ+i]-m1); lg[OUTSZ+i]=e1; s1+=e1;
    }
#pragma unroll
    for (int s=16;s;s>>=1){ s0+=__shfl_xor_sync(0xffffffffu,s0,s);
                            s1+=__shfl_xor_sync(0xffffffffu,s1,s); }
    __syncthreads();
    if (lane==0){ red[warp]=s0; red[16+warp]=s1; }
    __syncthreads();
    s0=red[0]; s1=red[16];
#pragma unroll
    for (int ww=1;ww<16;ww++){ s0+=red[ww]; s1+=red[16+ww]; }
    float inv0=1.0f/s0, inv1=1.0f/s1;
    for (int i=tid;i<OUTSZ;i+=512){
        out[(size_t)b0*OUTSZ+i]     = lg[i]*inv0;
        out[(size_t)(b0+1)*OUTSZ+i] = lg[OUTSZ+i]*inv1;
    }
}

// ---------------- launcher ----------------
extern "C" void kernel_launch(void* const* d_in, const int* in_sizes, int n_in,
                              void* d_out, int out_size){
    const float* x=(const float*)d_in[0];
    const float* wih=(const float*)d_in[1];
    const float* whh=(const float*)d_in[2];
    const float* bih=(const float*)d_in[3];
    const float* bhh=(const float*)d_in[4];
    const float* wd=(const float*)d_in[5];
    const float* bd=(const float*)d_in[6];
    float* out=(float*)d_out;

    int fsm = (128*LDA + 2*64*LDA)*2 + 128*LDC*4;      // 169984 B (gemm max)
    cudaFuncSetAttribute(k_fused, cudaFuncAttributeMaxDynamicSharedMemorySize, fsm);

    k_prep<<<512,256>>>(wih,whh,bih,bhh);
    k_fused<<<148,512,fsm>>>(x);
    k_dense2<<<BATCH/2,512>>>(wd,bd,out);
}